// round 1
// baseline (speedup 1.0000x reference)
#include <cuda_runtime.h>
#include <cstdint>

#define Bn 16
#define Cn 19
#define Hn 512
#define Wn 512
#define HWn (Hn * Wn)
#define NPIX (Bn * HWn)

__device__ double g_acc;
__device__ int g_is64;

// Detect whether targets arrived as int64 or int32, and zero the accumulator.
// int64 little-endian: word pairs are [value(<19), 0]. For int32 data the
// odd-index words are targets themselves, zero only with prob 1/19 each;
// all-128-zero has probability ~(1/19)^128 ~= 0. Deterministic per input.
__global__ void edgeloss_detect_init(const unsigned int* __restrict__ t) {
    if (threadIdx.x == 0 && blockIdx.x == 0) {
        bool is64 = true;
        for (int i = 0; i < 128; i++) {
            unsigned int lo = t[2 * i];
            unsigned int hi = t[2 * i + 1];
            if (hi != 0u || lo >= 19u) { is64 = false; break; }
        }
        g_is64 = is64 ? 1 : 0;
        g_acc = 0.0;
    }
}

template <typename T>
__device__ __forceinline__ float pixel_loss(const float* __restrict__ pred,
                                            const T* __restrict__ tg,
                                            int b, int h, int w, int hw) {
    const int base = b * HWn;
    const int c0 = (int)__ldg(&tg[base + hw]);

    // edge = any in-bounds 3x3 neighbor differs from center
    bool edge = false;
#pragma unroll
    for (int dy = -1; dy <= 1; dy++) {
#pragma unroll
        for (int dx = -1; dx <= 1; dx++) {
            if (dy == 0 && dx == 0) continue;
            int hh = h + dy, ww = w + dx;
            if (hh >= 0 && hh < Hn && ww >= 0 && ww < Wn) {
                edge |= ((int)__ldg(&tg[base + hh * Wn + ww]) != c0);
            }
        }
    }

    const float* p = pred + (size_t)b * Cn * HWn + hw;
    float v[Cn];
#pragma unroll
    for (int c = 0; c < Cn; c++) v[c] = __ldg(p + (size_t)c * HWn);

    float m = v[0];
#pragma unroll
    for (int c = 1; c < Cn; c++) m = fmaxf(m, v[c]);

    float s = 0.0f;
    float xt = v[0];
#pragma unroll
    for (int c = 0; c < Cn; c++) {
        s += __expf(v[c] - m);
        if (c == c0) xt = v[c];   // unrolled select, no dynamic reg indexing
    }

    float ce = __logf(s) + m - xt;
    float wgt = edge ? 2.0f : 1.0f;
    return ce * wgt;
}

__global__ void __launch_bounds__(256)
edgeloss_main(const float* __restrict__ pred, const void* __restrict__ targ_v) {
    int pix = blockIdx.x * blockDim.x + threadIdx.x;

    float val = 0.0f;
    if (pix < NPIX) {
        int b = pix / HWn;
        int hw = pix - b * HWn;
        int h = hw / Wn;
        int w = hw - h * Wn;
        if (g_is64) {
            val = pixel_loss<long long>(pred, (const long long*)targ_v, b, h, w, hw);
        } else {
            val = pixel_loss<int>(pred, (const int*)targ_v, b, h, w, hw);
        }
    }

    // block reduce
    const unsigned FULL = 0xFFFFFFFFu;
#pragma unroll
    for (int off = 16; off > 0; off >>= 1)
        val += __shfl_down_sync(FULL, val, off);

    __shared__ float smem[8];
    int lane = threadIdx.x & 31;
    int wid = threadIdx.x >> 5;
    if (lane == 0) smem[wid] = val;
    __syncthreads();
    if (wid == 0) {
        float bs = (lane < 8) ? smem[lane] : 0.0f;
#pragma unroll
        for (int off = 4; off > 0; off >>= 1)
            bs += __shfl_down_sync(FULL, bs, off);
        if (lane == 0) atomicAdd(&g_acc, (double)bs);
    }
}

__global__ void edgeloss_finalize(float* __restrict__ out) {
    if (threadIdx.x == 0 && blockIdx.x == 0) {
        out[0] = (float)(g_acc / (double)NPIX);
    }
}

extern "C" void kernel_launch(void* const* d_in, const int* in_sizes, int n_in,
                              void* d_out, int out_size) {
    const float* pred = (const float*)d_in[0];
    const void* targ = (const void*)d_in[1];
    float* out = (float*)d_out;

    edgeloss_detect_init<<<1, 32>>>((const unsigned int*)targ);
    edgeloss_main<<<NPIX / 256, 256>>>(pred, targ);
    edgeloss_finalize<<<1, 32>>>(out);
}